// round 8
// baseline (speedup 1.0000x reference)
#include <cuda_runtime.h>
#include <math.h>
#include <stdint.h>

#define NN 50000
#define NE 800000
#define D  128
#define DO 64
#define NC 40
#define SCAN_T 512
#define SCAN_B ((NN + SCAN_T - 1) / SCAN_T)   // 98

#define ASTR2 20   // uint2 stride per node (x-chunk paired layout)
#define WSTR2 132  // uint2 stride per pair-row (W paired layout)
#define ARSTR 132  // uint32 stride per node (resident agg layout)

// Scratch (device globals: no allocation allowed)
__device__ float g_x1[(size_t)NN * D];
__device__ float g_x2[(size_t)NN * D];
__device__ float g_p[(size_t)NN * DO];
__device__ float g_q[(size_t)NN * DO];
__device__ int   g_deg[NN];
__device__ int   g_off[NN];
__device__ int   g_cur[NN];
__device__ int   g_bsum[SCAN_B];
__device__ int   g_esrc[NE];

__device__ __forceinline__ float gelu_exact(float v) {
    return 0.5f * v * (1.0f + erff(v * 0.70710678118654752f));
}

__device__ __forceinline__ uint32_t f2tf32(float f) {
    uint32_t r;
    asm("cvt.rna.tf32.f32 %0, %1;" : "=r"(r) : "f"(f));
    return r;
}

__device__ __forceinline__ void mma_tf32(float* d,
    uint32_t a0, uint32_t a1, uint32_t a2, uint32_t a3,
    uint32_t b0, uint32_t b1)
{
    asm volatile(
        "mma.sync.aligned.m16n8k8.row.col.f32.tf32.tf32.f32 "
        "{%0,%1,%2,%3}, {%4,%5,%6,%7}, {%8,%9}, {%0,%1,%2,%3};"
        : "+f"(d[0]), "+f"(d[1]), "+f"(d[2]), "+f"(d[3])
        : "r"(a0), "r"(a1), "r"(a2), "r"(a3), "r"(b0), "r"(b1));
}

// ---------------- CSR build ----------------

__global__ void zero_deg_cur() {
    int i = blockIdx.x * blockDim.x + threadIdx.x;
    if (i < NN) { g_deg[i] = 0; g_cur[i] = 0; }
}

__global__ void count_deg(const int* __restrict__ dst) {
    int e = blockIdx.x * blockDim.x + threadIdx.x;
    if (e < NE) atomicAdd(&g_deg[dst[e]], 1);
}

__global__ void scan_local() {
    __shared__ int s[SCAN_T];
    int t = threadIdx.x;
    int i = blockIdx.x * SCAN_T + t;
    int v = (i < NN) ? g_deg[i] : 0;
    s[t] = v;
    __syncthreads();
    #pragma unroll
    for (int off = 1; off < SCAN_T; off <<= 1) {
        int a = (t >= off) ? s[t - off] : 0;
        __syncthreads();
        s[t] += a;
        __syncthreads();
    }
    if (i < NN) g_off[i] = s[t] - v;              // exclusive within block
    if (t == SCAN_T - 1) g_bsum[blockIdx.x] = s[t];
}

// Each block redundantly scans the 98 block sums, then applies to its slice.
__global__ void scan_add2() {   // <<<(NN+255)/256, 128>>>, 2 elems/thread
    __shared__ int s[128];
    int t = threadIdx.x;
    int v = (t < SCAN_B) ? g_bsum[t] : 0;
    s[t] = v;
    __syncthreads();
    #pragma unroll
    for (int off = 1; off < 128; off <<= 1) {
        int a = (t >= off) ? s[t - off] : 0;
        __syncthreads();
        s[t] += a;
        __syncthreads();
    }
    int inc = s[t];
    __syncthreads();
    s[t] = inc - v;                               // exclusive
    __syncthreads();
    int i0 = blockIdx.x * 256 + t;
    int i1 = i0 + 128;
    if (i0 < NN) g_off[i0] += s[i0 / SCAN_T];
    if (i1 < NN) g_off[i1] += s[i1 / SCAN_T];
}

__global__ void fill_edges(const int* __restrict__ src, const int* __restrict__ dst) {
    int e = blockIdx.x * blockDim.x + threadIdx.x;
    if (e >= NE) return;
    int d = dst[e];
    int pos = g_off[d] + atomicAdd(&g_cur[d], 1);
    g_esrc[pos] = src[e];
}

// ---- sage_fused: gather(mean) + tf32 MMA + LN/GELU/residual, one kernel ----
// Phase 1: 8 warps x 8 nodes each: gather mean of neighbor rows, write tf32
//          into resident smem Ar[64][ARSTR].
// Phase 2: h = [agg; x] @ [Wl; Wr] + bl -> LN -> GELU -> + x.
//          kc 0..3 read A from Ar; kc 4..7 stream x chunks through Apk.

__global__ __launch_bounds__(256, 2) void sage_fused(
    const float* __restrict__ xin,
    const float* __restrict__ Wl, const float* __restrict__ bl,
    const float* __restrict__ Wr,
    const float* __restrict__ gma, const float* __restrict__ bta,
    float* __restrict__ xout)
{
    extern __shared__ uint32_t smraw[];
    uint32_t* Ar = smraw;                          // 64*ARSTR u32  = 33792 B
    uint2*    Wpk = (uint2*)(Ar + 64 * ARSTR);     // 16*WSTR2 u2   = 16896 B
    uint2*    Apk = Wpk + 16 * WSTR2;              // 64*ASTR2 u2   = 10240 B
    float*    sred = (float*)(Apk + 64 * ASTR2);   // 4*64*2 f      =  2048 B

    const int tid = threadIdx.x;
    const int node0 = blockIdx.x * 64;
    const int warp = tid >> 5, lane = tid & 31;
    const int wm = warp & 1, wn = warp >> 1;
    const int g = lane >> 2, t4 = lane & 3;

    // ---------- phase 1: gather into Ar ----------
    {
        const float4* x4 = (const float4*)xin;
        for (int nn = 0; nn < 8; nn++) {
            int ln = warp * 8 + nn;
            int gn = node0 + ln;
            float4 a0 = make_float4(0.f,0.f,0.f,0.f), a1 = a0, a2 = a0, a3 = a0;
            float inv = 1.0f;
            if (gn < NN) {
                int start = g_off[gn], deg = g_deg[gn];
                const int* es = g_esrc + start;
                int e = 0;
                for (; e + 4 <= deg; e += 4) {
                    int s0 = __ldg(es + e),     s1 = __ldg(es + e + 1);
                    int s2 = __ldg(es + e + 2), s3 = __ldg(es + e + 3);
                    float4 v0 = __ldg(&x4[(size_t)s0 * 32 + lane]);
                    float4 v1 = __ldg(&x4[(size_t)s1 * 32 + lane]);
                    float4 v2 = __ldg(&x4[(size_t)s2 * 32 + lane]);
                    float4 v3 = __ldg(&x4[(size_t)s3 * 32 + lane]);
                    a0.x += v0.x; a0.y += v0.y; a0.z += v0.z; a0.w += v0.w;
                    a1.x += v1.x; a1.y += v1.y; a1.z += v1.z; a1.w += v1.w;
                    a2.x += v2.x; a2.y += v2.y; a2.z += v2.z; a2.w += v2.w;
                    a3.x += v3.x; a3.y += v3.y; a3.z += v3.z; a3.w += v3.w;
                }
                for (; e < deg; e++) {
                    int s0 = __ldg(es + e);
                    float4 v0 = __ldg(&x4[(size_t)s0 * 32 + lane]);
                    a0.x += v0.x; a0.y += v0.y; a0.z += v0.z; a0.w += v0.w;
                }
                inv = 1.0f / fmaxf((float)deg, 1.0f);
            }
            uint32_t* row = Ar + ln * ARSTR;
            row[4 * lane + 0] = f2tf32((a0.x + a1.x + a2.x + a3.x) * inv);
            row[4 * lane + 1] = f2tf32((a0.y + a1.y + a2.y + a3.y) * inv);
            row[4 * lane + 2] = f2tf32((a0.z + a1.z + a2.z + a3.z) * inv);
            row[4 * lane + 3] = f2tf32((a0.w + a1.w + a2.w + a3.w) * inv);
        }
    }

    // ---------- staging lambdas ----------
    const int an0 = tid >> 3, an1 = (tid + 256) >> 3, af = tid & 7;
    const int koff = (af >> 1) * 8 + (af & 1);
    const float4 f4z = make_float4(0.f, 0.f, 0.f, 0.f);

    auto ldX = [&](int c, float4& r0, float4& r1) {      // c = x chunk 0..3
        const float4* Asrc = (const float4*)xin;
        int kb = c * 8;
        int gn0 = node0 + an0, gn1 = node0 + an1;
        r0 = (gn0 < NN) ? __ldg(&Asrc[(size_t)gn0 * 32 + kb + af]) : f4z;
        r1 = (gn1 < NN) ? __ldg(&Asrc[(size_t)gn1 * 32 + kb + af]) : f4z;
    };
    auto stX = [&](float4 r0, float4 r1) {
        uint32_t* Au = (uint32_t*)Apk;
        Au[an0 * 40 + koff + 0] = f2tf32(r0.x);
        Au[an0 * 40 + koff + 2] = f2tf32(r0.y);
        Au[an0 * 40 + koff + 4] = f2tf32(r0.z);
        Au[an0 * 40 + koff + 6] = f2tf32(r0.w);
        Au[an1 * 40 + koff + 0] = f2tf32(r1.x);
        Au[an1 * 40 + koff + 2] = f2tf32(r1.y);
        Au[an1 * 40 + koff + 4] = f2tf32(r1.z);
        Au[an1 * 40 + koff + 6] = f2tf32(r1.w);
    };
    auto ldW = [&](int kc, float4* w) {
        const float4* Wsrc = (kc < 4) ? (const float4*)Wl : (const float4*)Wr;
        int kr0 = (kc & 3) * 32;
        int p0 = 2 * warp, p1 = 2 * warp + 1;
        int k0 = (p0 >> 2) * 8 + (p0 & 3);
        int k1 = (p1 >> 2) * 8 + (p1 & 3);
        w[0] = __ldg(&Wsrc[(size_t)(kr0 + k0) * 32 + lane]);
        w[1] = __ldg(&Wsrc[(size_t)(kr0 + k0 + 4) * 32 + lane]);
        w[2] = __ldg(&Wsrc[(size_t)(kr0 + k1) * 32 + lane]);
        w[3] = __ldg(&Wsrc[(size_t)(kr0 + k1 + 4) * 32 + lane]);
    };
    auto stW = [&](const float4* w) {
        uint4* W4 = (uint4*)Wpk;
        #pragma unroll
        for (int q = 0; q < 2; q++) {
            int p = 2 * warp + q;
            float4 lo = w[2 * q], hi = w[2 * q + 1];
            W4[p * 66 + 2 * lane]     = make_uint4(f2tf32(lo.x), f2tf32(hi.x),
                                                   f2tf32(lo.y), f2tf32(hi.y));
            W4[p * 66 + 2 * lane + 1] = make_uint4(f2tf32(lo.z), f2tf32(hi.z),
                                                   f2tf32(lo.w), f2tf32(hi.w));
        }
    };

    float acc0[4][4], acc1[4][4];
    #pragma unroll
    for (int i = 0; i < 4; i++)
        #pragma unroll
        for (int j = 0; j < 4; j++) { acc0[i][j] = 0.f; acc1[i][j] = 0.f; }

    {   // prefetch x chunk 0 (used at kc=4) and W chunk 0
        float4 x0, x1, w0[4];
        ldX(0, x0, x1); ldW(0, w0);
        stX(x0, x1); stW(w0);
    }
    __syncthreads();   // Ar + Apk + Wpk all visible

    const int C = wm * 32;
    for (int kc = 0; kc < 8; kc++) {
        float4 nx0, nx1, nw[4];
        bool ldx = (kc >= 4 && kc < 7);
        if (kc < 7) ldW(kc + 1, nw);
        if (ldx) ldX(kc - 3, nx0, nx1);
        if (kc < 4) {
            #pragma unroll
            for (int kk = 0; kk < 4; kk++) {
                int kb = kc * 32 + kk * 8 + t4;
                uint32_t a00 = Ar[(C + g)      * ARSTR + kb];
                uint32_t a10 = Ar[(C + g + 8)  * ARSTR + kb];
                uint32_t a20 = Ar[(C + g + 16) * ARSTR + kb];
                uint32_t a30 = Ar[(C + g + 24) * ARSTR + kb];
                uint32_t a01 = Ar[(C + g)      * ARSTR + kb + 4];
                uint32_t a11 = Ar[(C + g + 8)  * ARSTR + kb + 4];
                uint32_t a21 = Ar[(C + g + 16) * ARSTR + kb + 4];
                uint32_t a31 = Ar[(C + g + 24) * ARSTR + kb + 4];
                #pragma unroll
                for (int nt = 0; nt < 4; nt++) {
                    uint2 qb = Wpk[(kk * 4 + t4) * WSTR2 + wn * 32 + nt * 8 + g];
                    mma_tf32(acc0[nt], a00, a10, a01, a11, qb.x, qb.y);
                    mma_tf32(acc1[nt], a20, a30, a21, a31, qb.x, qb.y);
                }
            }
        } else {
            #pragma unroll
            for (int kk = 0; kk < 4; kk++) {
                int pbase = kk * 4 + t4;
                uint2 qa0 = Apk[(C + g)      * ASTR2 + pbase];
                uint2 qa1 = Apk[(C + g + 8)  * ASTR2 + pbase];
                uint2 qa2 = Apk[(C + g + 16) * ASTR2 + pbase];
                uint2 qa3 = Apk[(C + g + 24) * ASTR2 + pbase];
                #pragma unroll
                for (int nt = 0; nt < 4; nt++) {
                    uint2 qb = Wpk[pbase * WSTR2 + wn * 32 + nt * 8 + g];
                    mma_tf32(acc0[nt], qa0.x, qa1.x, qa0.y, qa1.y, qb.x, qb.y);
                    mma_tf32(acc1[nt], qa2.x, qa3.x, qa2.y, qa3.y, qb.x, qb.y);
                }
            }
        }
        __syncthreads();
        if (kc < 7) {
            stW(nw);
            if (ldx) stX(nx0, nx1);
            __syncthreads();
        }
    }

    // ---- epilogue: + bl -> LN (128 cols) -> GELU -> + residual ----
    float s[4][2];
    #pragma unroll
    for (int r = 0; r < 4; r++) { s[r][0] = 0.f; s[r][1] = 0.f; }
    #pragma unroll
    for (int nt = 0; nt < 4; nt++) {
        int c = wn * 32 + nt * 8 + 2 * t4;
        float2 blv = *(const float2*)&bl[c];
        acc0[nt][0] += blv.x; acc0[nt][1] += blv.y;
        acc0[nt][2] += blv.x; acc0[nt][3] += blv.y;
        acc1[nt][0] += blv.x; acc1[nt][1] += blv.y;
        acc1[nt][2] += blv.x; acc1[nt][3] += blv.y;
        s[0][0] += acc0[nt][0] + acc0[nt][1];
        s[0][1] += acc0[nt][0]*acc0[nt][0] + acc0[nt][1]*acc0[nt][1];
        s[1][0] += acc0[nt][2] + acc0[nt][3];
        s[1][1] += acc0[nt][2]*acc0[nt][2] + acc0[nt][3]*acc0[nt][3];
        s[2][0] += acc1[nt][0] + acc1[nt][1];
        s[2][1] += acc1[nt][0]*acc1[nt][0] + acc1[nt][1]*acc1[nt][1];
        s[3][0] += acc1[nt][2] + acc1[nt][3];
        s[3][1] += acc1[nt][2]*acc1[nt][2] + acc1[nt][3]*acc1[nt][3];
    }
    #pragma unroll
    for (int off = 1; off <= 2; off <<= 1)
        #pragma unroll
        for (int r = 0; r < 4; r++) {
            s[r][0] += __shfl_xor_sync(0xffffffffu, s[r][0], off);
            s[r][1] += __shfl_xor_sync(0xffffffffu, s[r][1], off);
        }
    if (t4 == 0) {
        #pragma unroll
        for (int r = 0; r < 4; r++) {
            sred[(wn * 64 + C + g + r * 8) * 2 + 0] = s[r][0];
            sred[(wn * 64 + C + g + r * 8) * 2 + 1] = s[r][1];
        }
    }
    __syncthreads();

    float mu[4], rs[4];
    #pragma unroll
    for (int r = 0; r < 4; r++) {
        int row = C + g + r * 8;
        float S1 = sred[(0 * 64 + row) * 2] + sred[(1 * 64 + row) * 2]
                 + sred[(2 * 64 + row) * 2] + sred[(3 * 64 + row) * 2];
        float S2 = sred[(0 * 64 + row) * 2 + 1] + sred[(1 * 64 + row) * 2 + 1]
                 + sred[(2 * 64 + row) * 2 + 1] + sred[(3 * 64 + row) * 2 + 1];
        mu[r] = S1 * (1.0f / 128.0f);
        float var = S2 * (1.0f / 128.0f) - mu[r] * mu[r];
        rs[r] = rsqrtf(var + 1e-5f);
    }

    #pragma unroll
    for (int nt = 0; nt < 4; nt++) {
        int c = wn * 32 + nt * 8 + 2 * t4;
        float2 gv = *(const float2*)&gma[c];
        float2 bv = *(const float2*)&bta[c];
        #pragma unroll
        for (int r = 0; r < 4; r++) {
            int gn = node0 + C + g + r * 8;
            if (gn >= NN) continue;
            float v0, v1;
            if (r == 0)      { v0 = acc0[nt][0]; v1 = acc0[nt][1]; }
            else if (r == 1) { v0 = acc0[nt][2]; v1 = acc0[nt][3]; }
            else if (r == 2) { v0 = acc1[nt][0]; v1 = acc1[nt][1]; }
            else             { v0 = acc1[nt][2]; v1 = acc1[nt][3]; }
            float2 res = *(const float2*)&xin[(size_t)gn * D + c];
            float o0 = gelu_exact((v0 - mu[r]) * rs[r] * gv.x + bv.x) + res.x;
            float o1 = gelu_exact((v1 - mu[r]) * rs[r] * gv.y + bv.y) + res.y;
            *(float2*)&xout[(size_t)gn * D + c] = make_float2(o0, o1);
        }
    }
}

// ---- gemm_pq: [p | q] = x2 @ [Wl3 | Wr3]  (tf32, K=128) ----

__global__ __launch_bounds__(256, 2) void gemm_pq(
    const float* __restrict__ Wl3, const float* __restrict__ Wr3)
{
    __shared__ uint2 Apk[64 * ASTR2];
    __shared__ uint2 Wpk[16 * WSTR2];

    const int tid = threadIdx.x;
    const int node0 = blockIdx.x * 64;
    const int warp = tid >> 5, lane = tid & 31;
    const int wm = warp & 1, wn = warp >> 1;
    const int g = lane >> 2, t4 = lane & 3;

    const int an0 = tid >> 3, an1 = (tid + 256) >> 3, af = tid & 7;
    const int koff = (af >> 1) * 8 + (af & 1);
    const float4 f4z = make_float4(0.f, 0.f, 0.f, 0.f);

    auto ldA = [&](int kc, float4& r0, float4& r1) {
        const float4* Asrc = (const float4*)g_x2;
        int kb = kc * 8;
        int gn0 = node0 + an0, gn1 = node0 + an1;
        r0 = (gn0 < NN) ? __ldg(&Asrc[(size_t)gn0 * 32 + kb + af]) : f4z;
        r1 = (gn1 < NN) ? __ldg(&Asrc[(size_t)gn1 * 32 + kb + af]) : f4z;
    };
    auto stA = [&](float4 r0, float4 r1) {
        uint32_t* Au = (uint32_t*)Apk;
        Au[an0 * 40 + koff + 0] = f2tf32(r0.x);
        Au[an0 * 40 + koff + 2] = f2tf32(r0.y);
        Au[an0 * 40 + koff + 4] = f2tf32(r0.z);
        Au[an0 * 40 + koff + 6] = f2tf32(r0.w);
        Au[an1 * 40 + koff + 0] = f2tf32(r1.x);
        Au[an1 * 40 + koff + 2] = f2tf32(r1.y);
        Au[an1 * 40 + koff + 4] = f2tf32(r1.z);
        Au[an1 * 40 + koff + 6] = f2tf32(r1.w);
    };
    auto ldW = [&](int kc, float4* w) {
        int kr0 = kc * 32;
        int p0 = 2 * warp, p1 = 2 * warp + 1;
        int k0 = (p0 >> 2) * 8 + (p0 & 3);
        int k1 = (p1 >> 2) * 8 + (p1 & 3);
        const float4* Wsrc = (lane < 16) ? (const float4*)Wl3 : (const float4*)Wr3;
        int cl = lane & 15;
        w[0] = __ldg(&Wsrc[(size_t)(kr0 + k0) * 16 + cl]);
        w[1] = __ldg(&Wsrc[(size_t)(kr0 + k0 + 4) * 16 + cl]);
        w[2] = __ldg(&Wsrc[(size_t)(kr0 + k1) * 16 + cl]);
        w[3] = __ldg(&Wsrc[(size_t)(kr0 + k1 + 4) * 16 + cl]);
    };
    auto stW = [&](const float4* w) {
        uint4* W4 = (uint4*)Wpk;
        #pragma unroll
        for (int q = 0; q < 2; q++) {
            int p = 2 * warp + q;
            float4 lo = w[2 * q], hi = w[2 * q + 1];
            W4[p * 66 + 2 * lane]     = make_uint4(f2tf32(lo.x), f2tf32(hi.x),
                                                   f2tf32(lo.y), f2tf32(hi.y));
            W4[p * 66 + 2 * lane + 1] = make_uint4(f2tf32(lo.z), f2tf32(hi.z),
                                                   f2tf32(lo.w), f2tf32(hi.w));
        }
    };

    float acc0[4][4], acc1[4][4];
    #pragma unroll
    for (int i = 0; i < 4; i++)
        #pragma unroll
        for (int j = 0; j < 4; j++) { acc0[i][j] = 0.f; acc1[i][j] = 0.f; }

    {
        float4 a0, a1, w0[4];
        ldA(0, a0, a1); ldW(0, w0);
        stA(a0, a1); stW(w0);
    }
    __syncthreads();

    const int C = wm * 32;
    for (int kc = 0; kc < 4; kc++) {
        float4 na0, na1, nw[4];
        if (kc < 3) { ldA(kc + 1, na0, na1); ldW(kc + 1, nw); }
        #pragma unroll
        for (int kk = 0; kk < 4; kk++) {
            int pbase = kk * 4 + t4;
            uint2 qa0 = Apk[(C + g)      * ASTR2 + pbase];
            uint2 qa1 = Apk[(C + g + 8)  * ASTR2 + pbase];
            uint2 qa2 = Apk[(C + g + 16) * ASTR2 + pbase];
            uint2 qa3 = Apk[(C + g + 24) * ASTR2 + pbase];
            #pragma unroll
            for (int nt = 0; nt < 4; nt++) {
                uint2 qb = Wpk[pbase * WSTR2 + wn * 32 + nt * 8 + g];
                mma_tf32(acc0[nt], qa0.x, qa1.x, qa0.y, qa1.y, qb.x, qb.y);
                mma_tf32(acc1[nt], qa2.x, qa3.x, qa2.y, qa3.y, qb.x, qb.y);
            }
        }
        __syncthreads();
        if (kc < 3) { stA(na0, na1); stW(nw); __syncthreads(); }
    }

    #pragma unroll
    for (int nt = 0; nt < 4; nt++) {
        int c = wn * 32 + nt * 8 + 2 * t4;
        float* dstbuf = (c < 64) ? g_p : g_q;
        int cc = c & 63;
        #pragma unroll
        for (int r = 0; r < 4; r++) {
            int gn = node0 + C + g + r * 8;
            if (gn >= NN) continue;
            float v0, v1;
            if (r == 0)      { v0 = acc0[nt][0]; v1 = acc0[nt][1]; }
            else if (r == 1) { v0 = acc0[nt][2]; v1 = acc0[nt][3]; }
            else if (r == 2) { v0 = acc1[nt][0]; v1 = acc1[nt][1]; }
            else             { v0 = acc1[nt][2]; v1 = acc1[nt][3]; }
            *(float2*)&dstbuf[(size_t)gn * DO + cc] = make_float2(v0, v1);
        }
    }
}

// ---- out_fused: gather(p) + gelu(+q+bl3) -> LN(64) -> @Wc + bcls ----
// warp per node; grid = ceil(NN/8), 256 threads.

__global__ __launch_bounds__(256) void out_fused(
    const float* __restrict__ bl3,
    const float* __restrict__ gc, const float* __restrict__ bc,
    const float* __restrict__ Wc, const float* __restrict__ bcls,
    float* __restrict__ out)
{
    __shared__ float Wcs[DO * NC];   // 10240 B
    __shared__ float bcs[NC];
    __shared__ float Vs[8][66];
    const int tid = threadIdx.x;
    const int warp = tid >> 5, lane = tid & 31;

    for (int i = tid; i < DO * NC; i += 256)
        Wcs[i] = __ldg(&Wc[i]);
    if (tid < NC) bcs[tid] = __ldg(&bcls[tid]);
    __syncthreads();

    int gn = blockIdx.x * 8 + warp;
    if (gn >= NN) return;

    // gather mean of p-neighbors (float2 slice per lane)
    int start = g_off[gn], deg = g_deg[gn];
    const int* es = g_esrc + start;
    const float2* p2 = (const float2*)g_p;
    float2 a0 = make_float2(0.f, 0.f), a1 = a0, a2 = a0, a3 = a0;
    int e = 0;
    for (; e + 4 <= deg; e += 4) {
        int s0 = __ldg(es + e),     s1 = __ldg(es + e + 1);
        int s2 = __ldg(es + e + 2), s3 = __ldg(es + e + 3);
        float2 v0 = __ldg(&p2[(size_t)s0 * 32 + lane]);
        float2 v1 = __ldg(&p2[(size_t)s1 * 32 + lane]);
        float2 v2 = __ldg(&p2[(size_t)s2 * 32 + lane]);
        float2 v3 = __ldg(&p2[(size_t)s3 * 32 + lane]);
        a0.x += v0.x; a0.y += v0.y;
        a1.x += v1.x; a1.y += v1.y;
        a2.x += v2.x; a2.y += v2.y;
        a3.x += v3.x; a3.y += v3.y;
    }
    for (; e < deg; e++) {
        int s0 = __ldg(es + e);
        float2 v0 = __ldg(&p2[(size_t)s0 * 32 + lane]);
        a0.x += v0.x; a0.y += v0.y;
    }
    float inv = 1.0f / fmaxf((float)deg, 1.0f);
    float agx = (a0.x + a1.x + a2.x + a3.x) * inv;
    float agy = (a0.y + a1.y + a2.y + a3.y) * inv;

    float2 q   = __ldg(&((const float2*)g_q)[(size_t)gn * 32 + lane]);
    float2 b3v = __ldg(&((const float2*)bl3)[lane]);
    float2 gcv = __ldg(&((const float2*)gc)[lane]);
    float2 bcv = __ldg(&((const float2*)bc)[lane]);

    float u0 = gelu_exact(agx + q.x + b3v.x);
    float u1 = gelu_exact(agy + q.y + b3v.y);
    float s1 = u0 + u1, s2 = u0 * u0 + u1 * u1;
    #pragma unroll
    for (int off = 16; off; off >>= 1) {
        s1 += __shfl_xor_sync(0xffffffffu, s1, off);
        s2 += __shfl_xor_sync(0xffffffffu, s2, off);
    }
    float mu = s1 * (1.0f / 64.0f);
    float var = s2 * (1.0f / 64.0f) - mu * mu;
    float rstd = rsqrtf(var + 1e-5f);
    Vs[warp][2 * lane]     = (u0 - mu) * rstd * gcv.x + bcv.x;
    Vs[warp][2 * lane + 1] = (u1 - mu) * rstd * gcv.y + bcv.y;
    __syncwarp();

    // classifier: lane -> col lane, and col lane+32 when <40
    float o1 = bcs[lane];
    float o2 = (lane < NC - 32) ? bcs[lane + 32] : 0.f;
    #pragma unroll 8
    for (int k = 0; k < DO; k++) {
        float vv = Vs[warp][k];
        o1 += vv * Wcs[k * NC + lane];
        if (lane < NC - 32) o2 += vv * Wcs[k * NC + lane + 32];
    }
    out[(size_t)gn * NC + lane] = o1;
    if (lane < NC - 32) out[(size_t)gn * NC + lane + 32] = o2;
}

// ---------------- launcher ----------------

extern "C" void kernel_launch(void* const* d_in, const int* in_sizes, int n_in,
                              void* d_out, int out_size)
{
    const float* x    = (const float*)d_in[0];
    const int*   ei   = (const int*)d_in[1];
    const float* Wl1  = (const float*)d_in[2];
    const float* bl1  = (const float*)d_in[3];
    const float* Wr1  = (const float*)d_in[4];
    const float* g1   = (const float*)d_in[5];
    const float* b1   = (const float*)d_in[6];
    const float* Wl2  = (const float*)d_in[7];
    const float* bl2  = (const float*)d_in[8];
    const float* Wr2  = (const float*)d_in[9];
    const float* g2   = (const float*)d_in[10];
    const float* b2   = (const float*)d_in[11];
    const float* Wl3  = (const float*)d_in[12];
    const float* bl3  = (const float*)d_in[13];
    const float* Wr3  = (const float*)d_in[14];
    const float* gc   = (const float*)d_in[15];
    const float* bc   = (const float*)d_in[16];
    const float* Wc   = (const float*)d_in[17];
    const float* bcls = (const float*)d_in[18];
    const int* src = ei;
    const int* dst = ei + NE;
    float* out = (float*)d_out;

    void *p_x1 = nullptr, *p_x2 = nullptr;
    cudaGetSymbolAddress(&p_x1, g_x1);
    cudaGetSymbolAddress(&p_x2, g_x2);

    const int smem_fused = (64 * ARSTR + 16 * WSTR2 * 2 + 64 * ASTR2 * 2) * 4 + 4 * 64 * 2 * 4; // 62976
    cudaFuncSetAttribute(sage_fused, cudaFuncAttributeMaxDynamicSharedMemorySize, smem_fused);

    const int nbn = (NN + 63) / 64;
    const int nbe = (NE + 255) / 256;

    // CSR build
    zero_deg_cur<<<(NN + 255) / 256, 256>>>();
    count_deg<<<nbe, 256>>>(dst);
    scan_local<<<SCAN_B, SCAN_T>>>();
    scan_add2<<<(NN + 255) / 256, 128>>>();
    fill_edges<<<nbe, 256>>>(src, dst);

    // Layer 1 + Layer 2 (gather fused into GEMM kernel)
    sage_fused<<<nbn, 256, smem_fused>>>(x, Wl1, bl1, Wr1, g1, b1, (float*)p_x1);
    sage_fused<<<nbn, 256, smem_fused>>>((const float*)p_x1, Wl2, bl2, Wr2, g2, b2, (float*)p_x2);

    // Layer 3: [p|q] = x2 @ [Wl3|Wr3], then fused gather+epilogue+classifier
    gemm_pq<<<nbn, 256>>>(Wl3, Wr3);
    out_fused<<<(NN + 7) / 8, 256>>>(bl3, gc, bc, Wc, bcls, out);
}

// round 9
// speedup vs baseline: 1.0232x; 1.0232x over previous
#include <cuda_runtime.h>
#include <math.h>
#include <stdint.h>

#define NN 50000
#define NE 800000
#define D  128
#define DO 64
#define NC 40
#define SCAN_T 512
#define SCAN_B ((NN + SCAN_T - 1) / SCAN_T)   // 98

#define ASTR2 20   // uint2 stride per node (paired A layout)
#define WSTR2 132  // uint2 stride per pair-row (paired W layout)

// Scratch (device globals: no allocation allowed)
__device__ float g_agg[(size_t)NN * D];
__device__ float g_x1[(size_t)NN * D];
__device__ float g_x2[(size_t)NN * D];
__device__ float g_p[(size_t)NN * DO];
__device__ float g_q[(size_t)NN * DO];
__device__ int   g_deg[NN];
__device__ int   g_off[NN];
__device__ int   g_cur[NN];
__device__ int   g_bsum[SCAN_B];
__device__ int   g_esrc[NE];

__device__ __forceinline__ float gelu_exact(float v) {
    return 0.5f * v * (1.0f + erff(v * 0.70710678118654752f));
}

__device__ __forceinline__ uint32_t f2tf32(float f) {
    uint32_t r;
    asm("cvt.rna.tf32.f32 %0, %1;" : "=r"(r) : "f"(f));
    return r;
}

__device__ __forceinline__ void mma_tf32(float* d,
    uint32_t a0, uint32_t a1, uint32_t a2, uint32_t a3,
    uint32_t b0, uint32_t b1)
{
    asm volatile(
        "mma.sync.aligned.m16n8k8.row.col.f32.tf32.tf32.f32 "
        "{%0,%1,%2,%3}, {%4,%5,%6,%7}, {%8,%9}, {%0,%1,%2,%3};"
        : "+f"(d[0]), "+f"(d[1]), "+f"(d[2]), "+f"(d[3])
        : "r"(a0), "r"(a1), "r"(a2), "r"(a3), "r"(b0), "r"(b1));
}

// ---------------- CSR build ----------------

__global__ void zero_deg_cur() {
    int i = blockIdx.x * blockDim.x + threadIdx.x;
    if (i < NN) { g_deg[i] = 0; g_cur[i] = 0; }
}

__global__ void count_deg(const int* __restrict__ dst) {
    int e = blockIdx.x * blockDim.x + threadIdx.x;
    if (e < NE) atomicAdd(&g_deg[dst[e]], 1);
}

__global__ void scan_local() {
    __shared__ int s[SCAN_T];
    int t = threadIdx.x;
    int i = blockIdx.x * SCAN_T + t;
    int v = (i < NN) ? g_deg[i] : 0;
    s[t] = v;
    __syncthreads();
    #pragma unroll
    for (int off = 1; off < SCAN_T; off <<= 1) {
        int a = (t >= off) ? s[t - off] : 0;
        __syncthreads();
        s[t] += a;
        __syncthreads();
    }
    if (i < NN) g_off[i] = s[t] - v;
    if (t == SCAN_T - 1) g_bsum[blockIdx.x] = s[t];
}

// Each block redundantly scans the 98 block sums, then applies to its slice.
__global__ void scan_add2() {   // <<<(NN+255)/256, 128>>>, 2 elems/thread
    __shared__ int s[128];
    int t = threadIdx.x;
    int v = (t < SCAN_B) ? g_bsum[t] : 0;
    s[t] = v;
    __syncthreads();
    #pragma unroll
    for (int off = 1; off < 128; off <<= 1) {
        int a = (t >= off) ? s[t - off] : 0;
        __syncthreads();
        s[t] += a;
        __syncthreads();
    }
    int inc = s[t];
    __syncthreads();
    s[t] = inc - v;                               // exclusive
    __syncthreads();
    int i0 = blockIdx.x * 256 + t;
    int i1 = i0 + 128;
    if (i0 < NN) g_off[i0] += s[i0 / SCAN_T];
    if (i1 < NN) g_off[i1] += s[i1 / SCAN_T];
}

__global__ void fill_edges(const int* __restrict__ src, const int* __restrict__ dst) {
    int e = blockIdx.x * blockDim.x + threadIdx.x;
    if (e >= NE) return;
    int d = dst[e];
    int pos = g_off[d] + atomicAdd(&g_cur[d], 1);
    g_esrc[pos] = src[e];
}

// ---------------- gather mean-aggregation (warp/node, 4-way unrolled) --------

__global__ __launch_bounds__(256) void gather128(const float* __restrict__ x) {
    int gw = (blockIdx.x * blockDim.x + threadIdx.x) >> 5;
    int lane = threadIdx.x & 31;
    if (gw >= NN) return;
    int start = g_off[gw], deg = g_deg[gw];
    const int* es = g_esrc + start;
    const float4* x4 = (const float4*)x;
    float4 a0 = make_float4(0.f,0.f,0.f,0.f), a1 = a0, a2 = a0, a3 = a0;
    int e = 0;
    for (; e + 4 <= deg; e += 4) {
        int s0 = __ldg(es + e),     s1 = __ldg(es + e + 1);
        int s2 = __ldg(es + e + 2), s3 = __ldg(es + e + 3);
        float4 v0 = __ldg(&x4[(size_t)s0 * 32 + lane]);
        float4 v1 = __ldg(&x4[(size_t)s1 * 32 + lane]);
        float4 v2 = __ldg(&x4[(size_t)s2 * 32 + lane]);
        float4 v3 = __ldg(&x4[(size_t)s3 * 32 + lane]);
        a0.x += v0.x; a0.y += v0.y; a0.z += v0.z; a0.w += v0.w;
        a1.x += v1.x; a1.y += v1.y; a1.z += v1.z; a1.w += v1.w;
        a2.x += v2.x; a2.y += v2.y; a2.z += v2.z; a2.w += v2.w;
        a3.x += v3.x; a3.y += v3.y; a3.z += v3.z; a3.w += v3.w;
    }
    for (; e < deg; e++) {
        int s0 = __ldg(es + e);
        float4 v0 = __ldg(&x4[(size_t)s0 * 32 + lane]);
        a0.x += v0.x; a0.y += v0.y; a0.z += v0.z; a0.w += v0.w;
    }
    float inv = 1.0f / fmaxf((float)deg, 1.0f);
    float4 r;
    r.x = (a0.x + a1.x + a2.x + a3.x) * inv;
    r.y = (a0.y + a1.y + a2.y + a3.y) * inv;
    r.z = (a0.z + a1.z + a2.z + a3.z) * inv;
    r.w = (a0.w + a1.w + a2.w + a3.w) * inv;
    ((float4*)g_agg)[(size_t)gw * 32 + lane] = r;
}

// ---- fused SAGE block: tf32 mma, 32x32 warp tiles, paired uint2 operands ----
// h = [agg; x] @ [Wl; Wr] + bl -> LN -> GELU -> + x.
// Block: 64 nodes x 128 cols; 8 warps: wm=warp&1 (32 nodes), wn=warp>>1 (32 cols).
// K streamed in chunks of 32. Paired smem layouts: one 64-bit LDS per fragment.

__global__ __launch_bounds__(256, 2) void sage_tc2(
    const float* __restrict__ xin,
    const float* __restrict__ Wl, const float* __restrict__ bl,
    const float* __restrict__ Wr,
    const float* __restrict__ gma, const float* __restrict__ bta,
    float* __restrict__ xout)
{
    __shared__ uint2 Apk[64 * ASTR2];     // 10240 B
    __shared__ uint2 Wpk[16 * WSTR2];     // 16896 B
    __shared__ float sred[4][64][2];      //  2048 B

    const int tid = threadIdx.x;
    const int node0 = blockIdx.x * 64;
    const int warp = tid >> 5, lane = tid & 31;
    const int wm = warp & 1, wn = warp >> 1;
    const int g = lane >> 2, t4 = lane & 3;

    const int an0 = tid >> 3, an1 = (tid + 256) >> 3, af = tid & 7;
    const int koff = (af >> 1) * 8 + (af & 1);
    const float4 f4z = make_float4(0.f, 0.f, 0.f, 0.f);

    auto ldA = [&](int kc, float4& r0, float4& r1) {
        const float4* Asrc = (kc < 4) ? (const float4*)g_agg : (const float4*)xin;
        int kb = (kc & 3) * 8;
        int gn0 = node0 + an0, gn1 = node0 + an1;
        r0 = (gn0 < NN) ? __ldg(&Asrc[(size_t)gn0 * 32 + kb + af]) : f4z;
        r1 = (gn1 < NN) ? __ldg(&Asrc[(size_t)gn1 * 32 + kb + af]) : f4z;
    };
    auto stA = [&](float4 r0, float4 r1) {
        uint32_t* Au = (uint32_t*)Apk;
        Au[an0 * 40 + koff + 0] = f2tf32(r0.x);
        Au[an0 * 40 + koff + 2] = f2tf32(r0.y);
        Au[an0 * 40 + koff + 4] = f2tf32(r0.z);
        Au[an0 * 40 + koff + 6] = f2tf32(r0.w);
        Au[an1 * 40 + koff + 0] = f2tf32(r1.x);
        Au[an1 * 40 + koff + 2] = f2tf32(r1.y);
        Au[an1 * 40 + koff + 4] = f2tf32(r1.z);
        Au[an1 * 40 + koff + 6] = f2tf32(r1.w);
    };
    auto ldW = [&](int kc, float4* w) {
        const float4* Wsrc = (kc < 4) ? (const float4*)Wl : (const float4*)Wr;
        int kr0 = (kc & 3) * 32;
        int p0 = 2 * warp, p1 = 2 * warp + 1;
        int k0 = (p0 >> 2) * 8 + (p0 & 3);
        int k1 = (p1 >> 2) * 8 + (p1 & 3);
        w[0] = __ldg(&Wsrc[(size_t)(kr0 + k0) * 32 + lane]);
        w[1] = __ldg(&Wsrc[(size_t)(kr0 + k0 + 4) * 32 + lane]);
        w[2] = __ldg(&Wsrc[(size_t)(kr0 + k1) * 32 + lane]);
        w[3] = __ldg(&Wsrc[(size_t)(kr0 + k1 + 4) * 32 + lane]);
    };
    auto stW = [&](const float4* w) {
        uint4* W4 = (uint4*)Wpk;
        #pragma unroll
        for (int q = 0; q < 2; q++) {
            int p = 2 * warp + q;
            float4 lo = w[2 * q], hi = w[2 * q + 1];
            W4[p * 66 + 2 * lane]     = make_uint4(f2tf32(lo.x), f2tf32(hi.x),
                                                   f2tf32(lo.y), f2tf32(hi.y));
            W4[p * 66 + 2 * lane + 1] = make_uint4(f2tf32(lo.z), f2tf32(hi.z),
                                                   f2tf32(lo.w), f2tf32(hi.w));
        }
    };

    float acc0[4][4], acc1[4][4];
    #pragma unroll
    for (int i = 0; i < 4; i++)
        #pragma unroll
        for (int j = 0; j < 4; j++) { acc0[i][j] = 0.f; acc1[i][j] = 0.f; }

    {
        float4 a0, a1, w0[4];
        ldA(0, a0, a1); ldW(0, w0);
        stA(a0, a1); stW(w0);
    }
    __syncthreads();

    const int C = wm * 32;
    for (int kc = 0; kc < 8; kc++) {
        float4 na0, na1, nw[4];
        if (kc < 7) { ldA(kc + 1, na0, na1); ldW(kc + 1, nw); }
        #pragma unroll
        for (int kk = 0; kk < 4; kk++) {
            int pbase = kk * 4 + t4;
            uint2 qa0 = Apk[(C + g)      * ASTR2 + pbase];
            uint2 qa1 = Apk[(C + g + 8)  * ASTR2 + pbase];
            uint2 qa2 = Apk[(C + g + 16) * ASTR2 + pbase];
            uint2 qa3 = Apk[(C + g + 24) * ASTR2 + pbase];
            #pragma unroll
            for (int nt = 0; nt < 4; nt++) {
                uint2 qb = Wpk[pbase * WSTR2 + wn * 32 + nt * 8 + g];
                mma_tf32(acc0[nt], qa0.x, qa1.x, qa0.y, qa1.y, qb.x, qb.y);
                mma_tf32(acc1[nt], qa2.x, qa3.x, qa2.y, qa3.y, qb.x, qb.y);
            }
        }
        __syncthreads();
        if (kc < 7) { stA(na0, na1); stW(nw); __syncthreads(); }
    }

    // ---- epilogue: + bl -> LN (128 cols) -> GELU -> + residual ----
    float s[4][2];
    #pragma unroll
    for (int r = 0; r < 4; r++) { s[r][0] = 0.f; s[r][1] = 0.f; }
    #pragma unroll
    for (int nt = 0; nt < 4; nt++) {
        int c = wn * 32 + nt * 8 + 2 * t4;
        float2 blv = *(const float2*)&bl[c];
        acc0[nt][0] += blv.x; acc0[nt][1] += blv.y;
        acc0[nt][2] += blv.x; acc0[nt][3] += blv.y;
        acc1[nt][0] += blv.x; acc1[nt][1] += blv.y;
        acc1[nt][2] += blv.x; acc1[nt][3] += blv.y;
        s[0][0] += acc0[nt][0] + acc0[nt][1];
        s[0][1] += acc0[nt][0]*acc0[nt][0] + acc0[nt][1]*acc0[nt][1];
        s[1][0] += acc0[nt][2] + acc0[nt][3];
        s[1][1] += acc0[nt][2]*acc0[nt][2] + acc0[nt][3]*acc0[nt][3];
        s[2][0] += acc1[nt][0] + acc1[nt][1];
        s[2][1] += acc1[nt][0]*acc1[nt][0] + acc1[nt][1]*acc1[nt][1];
        s[3][0] += acc1[nt][2] + acc1[nt][3];
        s[3][1] += acc1[nt][2]*acc1[nt][2] + acc1[nt][3]*acc1[nt][3];
    }
    #pragma unroll
    for (int off = 1; off <= 2; off <<= 1)
        #pragma unroll
        for (int r = 0; r < 4; r++) {
            s[r][0] += __shfl_xor_sync(0xffffffffu, s[r][0], off);
            s[r][1] += __shfl_xor_sync(0xffffffffu, s[r][1], off);
        }
    if (t4 == 0) {
        #pragma unroll
        for (int r = 0; r < 4; r++) {
            sred[wn][C + g + r * 8][0] = s[r][0];
            sred[wn][C + g + r * 8][1] = s[r][1];
        }
    }
    __syncthreads();

    float mu[4], rs[4];
    #pragma unroll
    for (int r = 0; r < 4; r++) {
        int row = C + g + r * 8;
        float S1 = sred[0][row][0] + sred[1][row][0] + sred[2][row][0] + sred[3][row][0];
        float S2 = sred[0][row][1] + sred[1][row][1] + sred[2][row][1] + sred[3][row][1];
        mu[r] = S1 * (1.0f / 128.0f);
        float var = S2 * (1.0f / 128.0f) - mu[r] * mu[r];
        rs[r] = rsqrtf(var + 1e-5f);
    }

    #pragma unroll
    for (int nt = 0; nt < 4; nt++) {
        int c = wn * 32 + nt * 8 + 2 * t4;
        float2 gv = *(const float2*)&gma[c];
        float2 bv = *(const float2*)&bta[c];
        #pragma unroll
        for (int r = 0; r < 4; r++) {
            int gn = node0 + C + g + r * 8;
            if (gn >= NN) continue;
            float v0, v1;
            if (r == 0)      { v0 = acc0[nt][0]; v1 = acc0[nt][1]; }
            else if (r == 1) { v0 = acc0[nt][2]; v1 = acc0[nt][3]; }
            else if (r == 2) { v0 = acc1[nt][0]; v1 = acc1[nt][1]; }
            else             { v0 = acc1[nt][2]; v1 = acc1[nt][3]; }
            float2 res = *(const float2*)&xin[(size_t)gn * D + c];
            float o0 = gelu_exact((v0 - mu[r]) * rs[r] * gv.x + bv.x) + res.x;
            float o1 = gelu_exact((v1 - mu[r]) * rs[r] * gv.y + bv.y) + res.y;
            *(float2*)&xout[(size_t)gn * D + c] = make_float2(o0, o1);
        }
    }
}

// ---- gemm_pq: [p | q] = x2 @ [Wl3 | Wr3]  (tf32, K=128) ----

__global__ __launch_bounds__(256, 2) void gemm_pq(
    const float* __restrict__ Wl3, const float* __restrict__ Wr3)
{
    __shared__ uint2 Apk[64 * ASTR2];
    __shared__ uint2 Wpk[16 * WSTR2];

    const int tid = threadIdx.x;
    const int node0 = blockIdx.x * 64;
    const int warp = tid >> 5, lane = tid & 31;
    const int wm = warp & 1, wn = warp >> 1;
    const int g = lane >> 2, t4 = lane & 3;

    const int an0 = tid >> 3, an1 = (tid + 256) >> 3, af = tid & 7;
    const int koff = (af >> 1) * 8 + (af & 1);
    const float4 f4z = make_float4(0.f, 0.f, 0.f, 0.f);

    auto ldA = [&](int kc, float4& r0, float4& r1) {
        const float4* Asrc = (const float4*)g_x2;
        int kb = kc * 8;
        int gn0 = node0 + an0, gn1 = node0 + an1;
        r0 = (gn0 < NN) ? __ldg(&Asrc[(size_t)gn0 * 32 + kb + af]) : f4z;
        r1 = (gn1 < NN) ? __ldg(&Asrc[(size_t)gn1 * 32 + kb + af]) : f4z;
    };
    auto stA = [&](float4 r0, float4 r1) {
        uint32_t* Au = (uint32_t*)Apk;
        Au[an0 * 40 + koff + 0] = f2tf32(r0.x);
        Au[an0 * 40 + koff + 2] = f2tf32(r0.y);
        Au[an0 * 40 + koff + 4] = f2tf32(r0.z);
        Au[an0 * 40 + koff + 6] = f2tf32(r0.w);
        Au[an1 * 40 + koff + 0] = f2tf32(r1.x);
        Au[an1 * 40 + koff + 2] = f2tf32(r1.y);
        Au[an1 * 40 + koff + 4] = f2tf32(r1.z);
        Au[an1 * 40 + koff + 6] = f2tf32(r1.w);
    };
    auto ldW = [&](int kc, float4* w) {
        int kr0 = kc * 32;
        int p0 = 2 * warp, p1 = 2 * warp + 1;
        int k0 = (p0 >> 2) * 8 + (p0 & 3);
        int k1 = (p1 >> 2) * 8 + (p1 & 3);
        const float4* Wsrc = (lane < 16) ? (const float4*)Wl3 : (const float4*)Wr3;
        int cl = lane & 15;
        w[0] = __ldg(&Wsrc[(size_t)(kr0 + k0) * 16 + cl]);
        w[1] = __ldg(&Wsrc[(size_t)(kr0 + k0 + 4) * 16 + cl]);
        w[2] = __ldg(&Wsrc[(size_t)(kr0 + k1) * 16 + cl]);
        w[3] = __ldg(&Wsrc[(size_t)(kr0 + k1 + 4) * 16 + cl]);
    };
    auto stW = [&](const float4* w) {
        uint4* W4 = (uint4*)Wpk;
        #pragma unroll
        for (int q = 0; q < 2; q++) {
            int p = 2 * warp + q;
            float4 lo = w[2 * q], hi = w[2 * q + 1];
            W4[p * 66 + 2 * lane]     = make_uint4(f2tf32(lo.x), f2tf32(hi.x),
                                                   f2tf32(lo.y), f2tf32(hi.y));
            W4[p * 66 + 2 * lane + 1] = make_uint4(f2tf32(lo.z), f2tf32(hi.z),
                                                   f2tf32(lo.w), f2tf32(hi.w));
        }
    };

    float acc0[4][4], acc1[4][4];
    #pragma unroll
    for (int i = 0; i < 4; i++)
        #pragma unroll
        for (int j = 0; j < 4; j++) { acc0[i][j] = 0.f; acc1[i][j] = 0.f; }

    {
        float4 a0, a1, w0[4];
        ldA(0, a0, a1); ldW(0, w0);
        stA(a0, a1); stW(w0);
    }
    __syncthreads();

    const int C = wm * 32;
    for (int kc = 0; kc < 4; kc++) {
        float4 na0, na1, nw[4];
        if (kc < 3) { ldA(kc + 1, na0, na1); ldW(kc + 1, nw); }
        #pragma unroll
        for (int kk = 0; kk < 4; kk++) {
            int pbase = kk * 4 + t4;
            uint2 qa0 = Apk[(C + g)      * ASTR2 + pbase];
            uint2 qa1 = Apk[(C + g + 8)  * ASTR2 + pbase];
            uint2 qa2 = Apk[(C + g + 16) * ASTR2 + pbase];
            uint2 qa3 = Apk[(C + g + 24) * ASTR2 + pbase];
            #pragma unroll
            for (int nt = 0; nt < 4; nt++) {
                uint2 qb = Wpk[pbase * WSTR2 + wn * 32 + nt * 8 + g];
                mma_tf32(acc0[nt], qa0.x, qa1.x, qa0.y, qa1.y, qb.x, qb.y);
                mma_tf32(acc1[nt], qa2.x, qa3.x, qa2.y, qa3.y, qb.x, qb.y);
            }
        }
        __syncthreads();
        if (kc < 3) { stA(na0, na1); stW(nw); __syncthreads(); }
    }

    #pragma unroll
    for (int nt = 0; nt < 4; nt++) {
        int c = wn * 32 + nt * 8 + 2 * t4;
        float* dstbuf = (c < 64) ? g_p : g_q;
        int cc = c & 63;
        #pragma unroll
        for (int r = 0; r < 4; r++) {
            int gn = node0 + C + g + r * 8;
            if (gn >= NN) continue;
            float v0, v1;
            if (r == 0)      { v0 = acc0[nt][0]; v1 = acc0[nt][1]; }
            else if (r == 1) { v0 = acc0[nt][2]; v1 = acc0[nt][3]; }
            else if (r == 2) { v0 = acc1[nt][0]; v1 = acc1[nt][1]; }
            else             { v0 = acc1[nt][2]; v1 = acc1[nt][3]; }
            *(float2*)&dstbuf[(size_t)gn * DO + cc] = make_float2(v0, v1);
        }
    }
}

// ---- out_fused: gather(p) + gelu(+q+bl3) -> LN(64) -> @Wc + bcls ----
// warp per node; grid = ceil(NN/8), 256 threads.

__global__ __launch_bounds__(256) void out_fused(
    const float* __restrict__ bl3,
    const float* __restrict__ gc, const float* __restrict__ bc,
    const float* __restrict__ Wc, const float* __restrict__ bcls,
    float* __restrict__ out)
{
    __shared__ float Wcs[DO * NC];   // 10240 B
    __shared__ float bcs[NC];
    __shared__ float Vs[8][66];
    const int tid = threadIdx.x;
    const int warp = tid >> 5, lane = tid & 31;

    for (int i = tid; i < DO * NC; i += 256)
        Wcs[i] = __ldg(&Wc[i]);
    if (tid < NC) bcs[tid] = __ldg(&bcls[tid]);
    __syncthreads();

    int gn = blockIdx.x * 8 + warp;
    if (gn >= NN) return;

    // gather mean of p-neighbors (float2 slice per lane)
    int start = g_off[gn], deg = g_deg[gn];
    const int* es = g_esrc + start;
    const float2* p2 = (const float2*)g_p;
    float2 a0 = make_float2(0.f, 0.f), a1 = a0, a2 = a0, a3 = a0;
    int e = 0;
    for (; e + 4 <= deg; e += 4) {
        int s0 = __ldg(es + e),     s1 = __ldg(es + e + 1);
        int s2 = __ldg(es + e + 2), s3 = __ldg(es + e + 3);
        float2 v0 = __ldg(&p2[(size_t)s0 * 32 + lane]);
        float2 v1 = __ldg(&p2[(size_t)s1 * 32 + lane]);
        float2 v2 = __ldg(&p2[(size_t)s2 * 32 + lane]);
        float2 v3 = __ldg(&p2[(size_t)s3 * 32 + lane]);
        a0.x += v0.x; a0.y += v0.y;
        a1.x += v1.x; a1.y += v1.y;
        a2.x += v2.x; a2.y += v2.y;
        a3.x += v3.x; a3.y += v3.y;
    }
    for (; e < deg; e++) {
        int s0 = __ldg(es + e);
        float2 v0 = __ldg(&p2[(size_t)s0 * 32 + lane]);
        a0.x += v0.x; a0.y += v0.y;
    }
    float inv = 1.0f / fmaxf((float)deg, 1.0f);
    float agx = (a0.x + a1.x + a2.x + a3.x) * inv;
    float agy = (a0.y + a1.y + a2.y + a3.y) * inv;

    float2 q   = __ldg(&((const float2*)g_q)[(size_t)gn * 32 + lane]);
    float2 b3v = __ldg(&((const float2*)bl3)[lane]);
    float2 gcv = __ldg(&((const float2*)gc)[lane]);
    float2 bcv = __ldg(&((const float2*)bc)[lane]);

    float u0 = gelu_exact(agx + q.x + b3v.x);
    float u1 = gelu_exact(agy + q.y + b3v.y);
    float s1 = u0 + u1, s2 = u0 * u0 + u1 * u1;
    #pragma unroll
    for (int off = 16; off; off >>= 1) {
        s1 += __shfl_xor_sync(0xffffffffu, s1, off);
        s2 += __shfl_xor_sync(0xffffffffu, s2, off);
    }
    float mu = s1 * (1.0f / 64.0f);
    float var = s2 * (1.0f / 64.0f) - mu * mu;
    float rstd = rsqrtf(var + 1e-5f);
    Vs[warp][2 * lane]     = (u0 - mu) * rstd * gcv.x + bcv.x;
    Vs[warp][2 * lane + 1] = (u1 - mu) * rstd * gcv.y + bcv.y;
    __syncwarp();

    // classifier: lane -> col lane, and col lane+32 when <40
    float o1 = bcs[lane];
    float o2 = (lane < NC - 32) ? bcs[lane + 32] : 0.f;
    #pragma unroll 8
    for (int k = 0; k < DO; k++) {
        float vv = Vs[warp][k];
        o1 += vv * Wcs[k * NC + lane];
        if (lane < NC - 32) o2 += vv * Wcs[k * NC + lane + 32];
    }
    out[(size_t)gn * NC + lane] = o1;
    if (lane < NC - 32) out[(size_t)gn * NC + lane + 32] = o2;
}

// ---------------- launcher ----------------

extern "C" void kernel_launch(void* const* d_in, const int* in_sizes, int n_in,
                              void* d_out, int out_size)
{
    const float* x    = (const float*)d_in[0];
    const int*   ei   = (const int*)d_in[1];
    const float* Wl1  = (const float*)d_in[2];
    const float* bl1  = (const float*)d_in[3];
    const float* Wr1  = (const float*)d_in[4];
    const float* g1   = (const float*)d_in[5];
    const float* b1   = (const float*)d_in[6];
    const float* Wl2  = (const float*)d_in[7];
    const float* bl2  = (const float*)d_in[8];
    const float* Wr2  = (const float*)d_in[9];
    const float* g2   = (const float*)d_in[10];
    const float* b2   = (const float*)d_in[11];
    const float* Wl3  = (const float*)d_in[12];
    const float* bl3  = (const float*)d_in[13];
    const float* Wr3  = (const float*)d_in[14];
    const float* gc   = (const float*)d_in[15];
    const float* bc   = (const float*)d_in[16];
    const float* Wc   = (const float*)d_in[17];
    const float* bcls = (const float*)d_in[18];
    const int* src = ei;
    const int* dst = ei + NE;
    float* out = (float*)d_out;

    void *p_x1 = nullptr, *p_x2 = nullptr;
    cudaGetSymbolAddress(&p_x1, g_x1);
    cudaGetSymbolAddress(&p_x2, g_x2);

    const int nbn = (NN + 63) / 64;
    const int nbe = (NE + 255) / 256;
    const int nbw = ((NN * 32) + 255) / 256;   // one warp per node

    // CSR build
    zero_deg_cur<<<(NN + 255) / 256, 256>>>();
    count_deg<<<nbe, 256>>>(dst);
    scan_local<<<SCAN_B, SCAN_T>>>();
    scan_add2<<<(NN + 255) / 256, 128>>>();
    fill_edges<<<nbe, 256>>>(src, dst);

    // Layer 1
    gather128<<<nbw, 256>>>(x);
    sage_tc2<<<nbn, 256>>>(x, Wl1, bl1, Wr1, g1, b1, (float*)p_x1);

    // Layer 2
    gather128<<<nbw, 256>>>((const float*)p_x1);
    sage_tc2<<<nbn, 256>>>((const float*)p_x1, Wl2, bl2, Wr2, g2, b2, (float*)p_x2);

    // Layer 3: [p|q] = x2 @ [Wl3|Wr3], then fused gather+epilogue+classifier
    gemm_pq<<<nbn, 256>>>(Wl3, Wr3);
    out_fused<<<(NN + 7) / 8, 256>>>(bl3, gc, bc, Wc, bcls, out);
}